// round 8
// baseline (speedup 1.0000x reference)
#include <cuda_runtime.h>

#define NN 50000
#define EE 800000
#define HD 128
#define NH 4
#define ND 32

typedef unsigned long long u64;

// ---------------- scratch (device globals; no allocation allowed) ----------
__device__ float g_feat[NN * HD];   // Wh for current layer (25.6 MB)
__device__ float g_el[NN * NH];     // a_l . Wh
__device__ float g_er[NN * NH];     // a_r . Wh
__device__ float g_h1[NN * HD];     // layer-1 output (post-ELU) (25.6 MB)
__device__ float g_e[EE * NH];      // exp(e) spill for deg>32 nodes (12.8 MB)
__device__ int   g_dsti[EE];        // decoded int32 dst (3.2 MB)
__device__ int   g_csr_src[EE];     // src ids sorted by dst (3.2 MB)
__device__ int   g_cnt[NN];         // degree histogram, then scatter cursors
__device__ int   g_off[NN + 1];     // CSR offsets (by dst)
__device__ int   g_is64;            // 1 if src/dst stored as int64

// ---------------- helpers ---------------------------------------------------
__device__ __forceinline__ float lrelu(float x) {
    return (x > 0.f) ? x : 0.2f * x;
}
__device__ __forceinline__ u64 fma2(u64 a, u64 b, u64 c) {
    u64 d;
    asm("fma.rn.f32x2 %0, %1, %2, %3;" : "=l"(d) : "l"(a), "l"(b), "l"(c));
    return d;
}
__device__ __forceinline__ u64 add2(u64 a, u64 b) {
    u64 d;
    asm("add.rn.f32x2 %0, %1, %2;" : "=l"(d) : "l"(a), "l"(b));
    return d;
}
__device__ __forceinline__ float sum2(u64 a) {
    float lo, hi;
    asm("mov.b64 {%0, %1}, %2;" : "=f"(lo), "=f"(hi) : "l"(a));
    return lo + hi;
}

// ---------------- CSR build --------------------------------------------------
// zero counters + detect int64 vs int32 edge indices (int32 misread as int64
// packs two random node ids -> out of [0, NN) almost surely).
__global__ void zero_cnt_kernel(const long long* __restrict__ src) {
    int i = blockIdx.x * blockDim.x + threadIdx.x;
    if (i < NN) g_cnt[i] = 0;
    if (i == 0) {
        bool is64 = true;
        for (int k = 0; k < 8; k++) {
            long long v = src[k];
            if (v < 0 || v >= NN) { is64 = false; break; }
        }
        g_is64 = is64 ? 1 : 0;
    }
}

// decode dst + degree histogram
__global__ void convert_kernel(const void* __restrict__ dst) {
    int e = blockIdx.x * blockDim.x + threadIdx.x;
    if (e >= EE) return;
    int t = g_is64 ? (int)((const long long*)dst)[e] : ((const int*)dst)[e];
    g_dsti[e] = t;
    atomicAdd(&g_cnt[t], 1);
}

// single-block fused exclusive scan over g_cnt -> g_off (+ cursor init)
#define STB 1024
__global__ void __launch_bounds__(STB) scan_fused_kernel() {
    __shared__ int sd[STB];
    const int tid = threadIdx.x;
    const int per = (NN + STB - 1) / STB;          // 49
    const int start = tid * per;
    const int end = (start + per < NN) ? start + per : NN;

    int s = 0;
    for (int i = start; i < end; i++) s += g_cnt[i];
    sd[tid] = s;
    __syncthreads();
    for (int off = 1; off < STB; off <<= 1) {
        int t = (tid >= off) ? sd[tid - off] : 0;
        __syncthreads();
        sd[tid] += t;
        __syncthreads();
    }
    int run = sd[tid] - s;                          // exclusive base
    for (int i = start; i < end; i++) {
        int v = g_cnt[i];
        g_off[i] = run;
        g_cnt[i] = run;                             // becomes scatter cursor
        run += v;
    }
    if (tid == 0) g_off[NN] = EE;
}

__global__ void scatter_kernel(const void* __restrict__ src) {
    int e = blockIdx.x * blockDim.x + threadIdx.x;
    if (e >= EE) return;
    int s = g_is64 ? (int)((const long long*)src)[e] : ((const int*)src)[e];
    int t = g_dsti[e];
    int pos = atomicAdd(&g_cnt[t], 1);
    g_csr_src[pos] = s;
}

// ---------------- GEMM: feat = x @ W^T, plus el/er epilogue -----------------
// Block = 128 threads (thread j owns output column j).
// W row j in registers as 64 packed f32x2; x rows broadcast from smem.
// Result rows are staged in smem (fs) and the el/er dot-products are computed
// by a conflict-free staggered smem pass (no shfl chains).
// xin == nullptr means "read layer-1 output g_h1".
#define NPB 32
__global__ void __launch_bounds__(128) gemm_kernel(
    const float* __restrict__ xin, const float* __restrict__ W,
    const float* __restrict__ al, const float* __restrict__ ar)
{
    __shared__ float xs[NPB][HD];
    __shared__ float fs[NPB][HD];
    const float* xp = xin ? xin : (const float*)g_h1;
    const int j = threadIdx.x;
    const int node0 = blockIdx.x * NPB;

    u64 w2[HD / 2];
    const ulonglong2* Wv = (const ulonglong2*)(W + j * HD);
#pragma unroll
    for (int k = 0; k < HD / 4; k++) {
        ulonglong2 v = Wv[k];
        w2[2 * k + 0] = v.x;
        w2[2 * k + 1] = v.y;
    }

    // stage NPB node rows (vectorized)
    {
        const int nvec = NPB * HD / 4;           // float4 count
        float4* xsv = (float4*)xs;
        for (int i = threadIdx.x; i < nvec; i += 128) {
            int node = node0 + (i >> 5);          // 32 float4 per row
            xsv[i] = (node < NN) ? ((const float4*)xp)[(size_t)node * 32 + (i & 31)]
                                 : make_float4(0.f, 0.f, 0.f, 0.f);
        }
    }
    __syncthreads();

    for (int n = 0; n < NPB; n++) {
        int node = node0 + n;
        if (node >= NN) break;
        const ulonglong2* xv = (const ulonglong2*)xs[n];
        u64 a0 = 0ull, a1 = 0ull, a2 = 0ull, a3 = 0ull;  // {0.f,0.f} packed
#pragma unroll
        for (int k = 0; k < HD / 8; k++) {
            ulonglong2 xa = xv[2 * k + 0];
            ulonglong2 xb = xv[2 * k + 1];
            a0 = fma2(xa.x, w2[4 * k + 0], a0);
            a1 = fma2(xa.y, w2[4 * k + 1], a1);
            a2 = fma2(xb.x, w2[4 * k + 2], a2);
            a3 = fma2(xb.y, w2[4 * k + 3], a3);
        }
        float acc = sum2(add2(add2(a0, a1), add2(a2, a3)));
        g_feat[(size_t)node * HD + j] = acc;
        fs[n][j] = acc;
    }
    __syncthreads();

    // ---- el/er epilogue: thread (n,h) does two 32-length smem dots ----
    {
        const int n = j >> 2, h = j & 3;
        int node = node0 + n;
        if (node < NN) {
            const float* av = al + h * ND;
            const float* rv = ar + h * ND;
            const float* fv = fs[n] + h * ND;
            float el = 0.f, er = 0.f;
#pragma unroll
            for (int kk = 0; kk < ND; kk++) {
                int k = (kk + j) & (ND - 1);      // stagger: conflict-free
                float f = fv[k];
                el = fmaf(f, av[k], el);
                er = fmaf(f, rv[k], er);
            }
            g_el[node * NH + h] = el;
            g_er[node * NH + h] = er;
        }
    }
}

// ---------------- fused edge softmax + aggregate (warp per dst node) --------
// Softmax without max subtraction (|e| is small here; exp(e)/sum(exp(e)) is
// exactly the reference value mathematically).
// out == nullptr: layer 1 -> write elu(acc) to g_h1.
// else: layer 2 -> elu + mean over heads -> out [N, D].
__global__ void __launch_bounds__(256) gat_edge_kernel(float* __restrict__ out)
{
    __shared__ int   ssrc[8][32];
    __shared__ float salpha[8][32][4];

    const int w = threadIdx.x >> 5;
    int t = blockIdx.x * 8 + w;
    if (t >= NN) return;
    const int lane = threadIdx.x & 31;
    const int beg = g_off[t], end = g_off[t + 1];
    const int deg = end - beg;
    const int h = lane >> 3;

    float4 acc = {0.f, 0.f, 0.f, 0.f};

    if (deg > 0) {
        float4 er4 = *(const float4*)(g_er + t * NH);  // broadcast
        const bool small = (deg <= 32);

        // ---- phase 1: ex = exp(lrelu(el+er)); sum denominators ----
        float4 d4 = {0.f, 0.f, 0.f, 0.f};
        int s_my = 0;
        float4 ex_my = {0.f, 0.f, 0.f, 0.f};

        int i0 = beg + lane;
        if (i0 < end) {
            s_my = __ldg(&g_csr_src[i0]);
            float4 l4 = *(const float4*)(g_el + s_my * NH);
            ex_my.x = __expf(lrelu(l4.x + er4.x));
            ex_my.y = __expf(lrelu(l4.y + er4.y));
            ex_my.z = __expf(lrelu(l4.z + er4.z));
            ex_my.w = __expf(lrelu(l4.w + er4.w));
            d4 = ex_my;
            if (!small) *(float4*)(g_e + (size_t)i0 * NH) = ex_my;
        }
        if (!small) {
            for (int i = i0 + 32; i < end; i += 32) {
                int s = __ldg(&g_csr_src[i]);
                float4 l4 = *(const float4*)(g_el + s * NH);
                float4 ex;
                ex.x = __expf(lrelu(l4.x + er4.x));
                ex.y = __expf(lrelu(l4.y + er4.y));
                ex.z = __expf(lrelu(l4.z + er4.z));
                ex.w = __expf(lrelu(l4.w + er4.w));
                d4.x += ex.x; d4.y += ex.y; d4.z += ex.z; d4.w += ex.w;
                *(float4*)(g_e + (size_t)i * NH) = ex;
            }
        }
#pragma unroll
        for (int off = 16; off; off >>= 1) {
            d4.x += __shfl_xor_sync(0xffffffffu, d4.x, off);
            d4.y += __shfl_xor_sync(0xffffffffu, d4.y, off);
            d4.z += __shfl_xor_sync(0xffffffffu, d4.z, off);
            d4.w += __shfl_xor_sync(0xffffffffu, d4.w, off);
        }
        float4 rd4;
        rd4.x = __frcp_rn(d4.x); rd4.y = __frcp_rn(d4.y);
        rd4.z = __frcp_rn(d4.z); rd4.w = __frcp_rn(d4.w);

        // ---- phase 2: aggregation via smem-staged (src, alpha) ----
        if (small) {
            if (lane < deg) {
                ssrc[w][lane] = s_my;
                salpha[w][lane][0] = ex_my.x * rd4.x;
                salpha[w][lane][1] = ex_my.y * rd4.y;
                salpha[w][lane][2] = ex_my.z * rd4.z;
                salpha[w][lane][3] = ex_my.w * rd4.w;
            }
            __syncwarp();
            for (int i = 0; i < deg; i++) {
                int si = ssrc[w][i];
                float alpha = salpha[w][i][h];
                float4 f = *(const float4*)(g_feat + (size_t)si * HD + lane * 4);
                acc.x = fmaf(f.x, alpha, acc.x);
                acc.y = fmaf(f.y, alpha, acc.y);
                acc.z = fmaf(f.z, alpha, acc.z);
                acc.w = fmaf(f.w, alpha, acc.w);
            }
        } else {
            for (int base = beg; base < end; base += 32) {
                int n = min(32, end - base);
                if (lane < n) {
                    int i = base + lane;
                    int s = __ldg(&g_csr_src[i]);
                    float4 ex = *(const float4*)(g_e + (size_t)i * NH);
                    ssrc[w][lane] = s;
                    salpha[w][lane][0] = ex.x * rd4.x;
                    salpha[w][lane][1] = ex.y * rd4.y;
                    salpha[w][lane][2] = ex.z * rd4.z;
                    salpha[w][lane][3] = ex.w * rd4.w;
                }
                __syncwarp();
                for (int i = 0; i < n; i++) {
                    int si = ssrc[w][i];
                    float alpha = salpha[w][i][h];
                    float4 f = *(const float4*)(g_feat + (size_t)si * HD + lane * 4);
                    acc.x = fmaf(f.x, alpha, acc.x);
                    acc.y = fmaf(f.y, alpha, acc.y);
                    acc.z = fmaf(f.z, alpha, acc.z);
                    acc.w = fmaf(f.w, alpha, acc.w);
                }
                __syncwarp();
            }
        }
    }

    // ---- epilogue: ELU (+ head-mean for layer 2) ----
    acc.x = (acc.x > 0.f) ? acc.x : expm1f(acc.x);
    acc.y = (acc.y > 0.f) ? acc.y : expm1f(acc.y);
    acc.z = (acc.z > 0.f) ? acc.z : expm1f(acc.z);
    acc.w = (acc.w > 0.f) ? acc.w : expm1f(acc.w);

    if (out == nullptr) {
        *(float4*)(g_h1 + (size_t)t * HD + lane * 4) = acc;
    } else {
        // sum over heads: lanes l, l^8, l^16, l^24 hold same dims across heads
#pragma unroll
        for (int off = 8; off <= 16; off <<= 1) {
            acc.x += __shfl_xor_sync(0xffffffffu, acc.x, off);
            acc.y += __shfl_xor_sync(0xffffffffu, acc.y, off);
            acc.z += __shfl_xor_sync(0xffffffffu, acc.z, off);
            acc.w += __shfl_xor_sync(0xffffffffu, acc.w, off);
        }
        if (lane < 8) {
            float4 o;
            o.x = 0.25f * acc.x; o.y = 0.25f * acc.y;
            o.z = 0.25f * acc.z; o.w = 0.25f * acc.w;
            *(float4*)(out + t * ND + lane * 4) = o;
        }
    }
}

// ---------------- launch ----------------------------------------------------
extern "C" void kernel_launch(void* const* d_in, const int* in_sizes, int n_in,
                              void* d_out, int out_size)
{
    const float* x   = (const float*)d_in[0];
    const void*  src = d_in[1];
    const void*  dst = d_in[2];
    const float* W1  = (const float*)d_in[3];
    const float* al1 = (const float*)d_in[4];
    const float* ar1 = (const float*)d_in[5];
    const float* W2  = (const float*)d_in[6];
    const float* al2 = (const float*)d_in[7];
    const float* ar2 = (const float*)d_in[8];
    float* out = (float*)d_out;

    const int edge_blocks = (EE + 255) / 256;
    const int node_blocks = (NN + 255) / 256;
    const int gemm_blocks = (NN + NPB - 1) / NPB;
    const int gat_blocks  = (NN + 7) / 8;

    // CSR build interleaved with layer-1 GEMM (gemm is independent of CSR;
    // placing it 4th also puts it under the ncu sampler).
    zero_cnt_kernel<<<node_blocks, 256>>>((const long long*)src);
    convert_kernel<<<edge_blocks, 256>>>(dst);
    scan_fused_kernel<<<1, STB>>>();
    gemm_kernel<<<gemm_blocks, 128>>>(x, W1, al1, ar1);
    scatter_kernel<<<edge_blocks, 256>>>(src);

    gat_edge_kernel<<<gat_blocks, 256>>>(nullptr);

    gemm_kernel<<<gemm_blocks, 128>>>(nullptr, W2, al2, ar2);
    gat_edge_kernel<<<gat_blocks, 256>>>(out);

    (void)in_sizes; (void)n_in; (void)out_size;
}

// round 9
// speedup vs baseline: 1.2621x; 1.2621x over previous
#include <cuda_runtime.h>

#define NN 50000
#define EE 800000
#define HD 128
#define NH 4
#define ND 32
#define GN 64          // nodes per gemm block

typedef unsigned long long u64;

// ---------------- scratch (device globals; no allocation allowed) ----------
__device__ float g_feat[NN * HD];   // Wh for current layer (25.6 MB)
__device__ float g_el[NN * NH];     // a_l . Wh
__device__ float g_er[NN * NH];     // a_r . Wh
__device__ float g_h1[NN * HD];     // layer-1 output (post-ELU) (25.6 MB)
__device__ float g_e[EE * NH];      // exp(e) spill for deg>32 nodes (12.8 MB)
__device__ int   g_dsti[EE];        // decoded int32 dst (3.2 MB)
__device__ int   g_csr_src[EE];     // src ids sorted by dst (3.2 MB)
__device__ int   g_cnt[NN];         // degree histogram, then scatter cursors
__device__ int   g_off[NN + 1];     // CSR offsets (by dst)
__device__ int   g_is64;            // 1 if src/dst stored as int64

// ---------------- helpers ---------------------------------------------------
__device__ __forceinline__ float lrelu(float x) {
    return (x > 0.f) ? x : 0.2f * x;
}
__device__ __forceinline__ u64 fma2(u64 a, u64 b, u64 c) {
    u64 d;
    asm("fma.rn.f32x2 %0, %1, %2, %3;" : "=l"(d) : "l"(a), "l"(b), "l"(c));
    return d;
}
__device__ __forceinline__ float sum2(u64 a) {
    float lo, hi;
    asm("mov.b64 {%0, %1}, %2;" : "=f"(lo), "=f"(hi) : "l"(a));
    return lo + hi;
}
__device__ __forceinline__ u64 pack2(float lo, float hi) {
    u64 d;
    asm("mov.b64 %0, {%1, %2};" : "=l"(d) : "f"(lo), "f"(hi));
    return d;
}

// ---------------- CSR build --------------------------------------------------
__global__ void zero_cnt_kernel(const long long* __restrict__ src) {
    int i = blockIdx.x * blockDim.x + threadIdx.x;
    if (i < NN) g_cnt[i] = 0;
    if (i == 0) {
        bool is64 = true;
        for (int k = 0; k < 8; k++) {
            long long v = src[k];
            if (v < 0 || v >= NN) { is64 = false; break; }
        }
        g_is64 = is64 ? 1 : 0;
    }
}

__global__ void convert_kernel(const void* __restrict__ dst) {
    int e = blockIdx.x * blockDim.x + threadIdx.x;
    if (e >= EE) return;
    int t = g_is64 ? (int)((const long long*)dst)[e] : ((const int*)dst)[e];
    g_dsti[e] = t;
    atomicAdd(&g_cnt[t], 1);
}

// single-block fused exclusive scan over g_cnt -> g_off (+ cursor init)
#define STB 1024
__global__ void __launch_bounds__(STB) scan_fused_kernel() {
    __shared__ int sd[STB];
    const int tid = threadIdx.x;
    const int per = (NN + STB - 1) / STB;          // 49
    const int start = tid * per;
    const int end = (start + per < NN) ? start + per : NN;

    int s = 0;
    for (int i = start; i < end; i++) s += g_cnt[i];
    sd[tid] = s;
    __syncthreads();
    for (int off = 1; off < STB; off <<= 1) {
        int t = (tid >= off) ? sd[tid - off] : 0;
        __syncthreads();
        sd[tid] += t;
        __syncthreads();
    }
    int run = sd[tid] - s;                          // exclusive base
    for (int i = start; i < end; i++) {
        int v = g_cnt[i];
        g_off[i] = run;
        g_cnt[i] = run;                             // becomes scatter cursor
        run += v;
    }
    if (tid == 0) g_off[NN] = EE;
}

__global__ void scatter_kernel(const void* __restrict__ src) {
    int e = blockIdx.x * blockDim.x + threadIdx.x;
    if (e >= EE) return;
    int s = g_is64 ? (int)((const long long*)src)[e] : ((const int*)src)[e];
    int t = g_dsti[e];
    int pos = atomicAdd(&g_cnt[t], 1);
    g_csr_src[pos] = s;
}

// ---------------- GEMM: feat = x @ W^T (register-tiled, packed-k fma2) ------
// Block: 64 nodes x 128 cols, 256 threads = 16(tx: col groups) x 16(ty: node
// groups). Thread computes 4 nodes x 8 cols; cols strided: j = tx + 16*jj.
// Accumulators are k-paired f32x2 (lanes = even/odd k partials).
// W is staged per 32-k chunk into smem TRANSPOSED as u64 (k,k+1) pairs with
// XOR swizzle ws2[k2][j ^ k2] -> conflict-free compute reads.
// el/er epilogue via half-warp shfl reduction.
// xin == nullptr means "read layer-1 output g_h1".
__global__ void __launch_bounds__(256, 2) gemm_kernel(
    const float* __restrict__ xin, const float* __restrict__ W,
    const float* __restrict__ al, const float* __restrict__ ar)
{
    __shared__ __align__(16) float xs[GN][HD];     // 32 KB
    __shared__ __align__(16) u64 ws2[16][HD];      // 16 KB (one 32-k chunk)

    const float* xp = xin ? xin : (const float*)g_h1;
    const int tid = threadIdx.x;
    const int tx = tid & 15;
    const int ty = tid >> 4;
    const int node0 = blockIdx.x * GN;

    // ---- load X tile: 64 rows x 128 floats (2048 float4, 8 per thread) ----
    for (int it = 0; it < 8; it++) {
        int idx = it * 256 + tid;
        int row = idx >> 5, c4 = idx & 31;
        int node = node0 + row;
        float4 v = (node < NN) ? ((const float4*)xp)[(size_t)node * 32 + c4]
                               : make_float4(0.f, 0.f, 0.f, 0.f);
        *(float4*)&xs[row][c4 * 4] = v;
    }

    u64 acc2[4][8];
#pragma unroll
    for (int i = 0; i < 4; i++)
#pragma unroll
        for (int jj = 0; jj < 8; jj++) acc2[i][jj] = 0ull;

    for (int ch = 0; ch < 4; ch++) {
        __syncthreads();   // xs ready (first iter) / ws2 drained (later iters)
        // ---- load W chunk: rows j 0..127, k in [ch*32, ch*32+32) ----
        for (int it = 0; it < 4; it++) {
            int idx = it * 256 + tid;
            int j = idx >> 3, c8 = idx & 7;
            float4 v = ((const float4*)W)[j * 32 + ch * 8 + c8];
            int k2a = c8 * 2, k2b = k2a + 1;
            ws2[k2a][j ^ k2a] = pack2(v.x, v.y);
            ws2[k2b][j ^ k2b] = pack2(v.z, v.w);
        }
        __syncthreads();
        // ---- compute 16 k2 steps ----
#pragma unroll
        for (int q = 0; q < 16; q++) {
            int txs = tx ^ q;
            u64 w2[8];
#pragma unroll
            for (int jj = 0; jj < 8; jj++) w2[jj] = ws2[q][txs + 16 * jj];
#pragma unroll
            for (int i = 0; i < 4; i++) {
                u64 x2 = *(const u64*)&xs[ty * 4 + i][ch * 32 + q * 2];
#pragma unroll
                for (int jj = 0; jj < 8; jj++)
                    acc2[i][jj] = fma2(x2, w2[jj], acc2[i][jj]);
            }
        }
    }

    // ---- fold k-pairs, store feat, compute el/er ----
    float a_l[8], a_r[8];
#pragma unroll
    for (int jj = 0; jj < 8; jj++) {
        a_l[jj] = __ldg(&al[tx + 16 * jj]);
        a_r[jj] = __ldg(&ar[tx + 16 * jj]);
    }

#pragma unroll
    for (int i = 0; i < 4; i++) {
        int node = node0 + ty * 4 + i;
        float f[8];
#pragma unroll
        for (int jj = 0; jj < 8; jj++) f[jj] = sum2(acc2[i][jj]);
        if (node < NN) {
#pragma unroll
            for (int jj = 0; jj < 8; jj++)
                g_feat[(size_t)node * HD + tx + 16 * jj] = f[jj];
        }
        // head h owns jj = 2h, 2h+1  (j = tx+32h and tx+16+32h)
        float elp[4], erp[4];
#pragma unroll
        for (int h = 0; h < 4; h++) {
            elp[h] = f[2 * h] * a_l[2 * h] + f[2 * h + 1] * a_l[2 * h + 1];
            erp[h] = f[2 * h] * a_r[2 * h] + f[2 * h + 1] * a_r[2 * h + 1];
        }
        // reduce across the 16 tx lanes (xor offsets < 16 stay in half-warp)
#pragma unroll
        for (int off = 8; off; off >>= 1) {
#pragma unroll
            for (int h = 0; h < 4; h++) {
                elp[h] += __shfl_xor_sync(0xffffffffu, elp[h], off);
                erp[h] += __shfl_xor_sync(0xffffffffu, erp[h], off);
            }
        }
        if (tx == 0 && node < NN) {
#pragma unroll
            for (int h = 0; h < 4; h++) {
                g_el[node * NH + h] = elp[h];
                g_er[node * NH + h] = erp[h];
            }
        }
    }
}

// ---------------- fused edge softmax + aggregate (warp per dst node) --------
// Softmax without max subtraction (|e| is small; exp(e)/sum(exp(e)) matches
// the reference value mathematically).
__global__ void __launch_bounds__(256) gat_edge_kernel(float* __restrict__ out)
{
    __shared__ int   ssrc[8][32];
    __shared__ float salpha[8][32][4];

    const int w = threadIdx.x >> 5;
    int t = blockIdx.x * 8 + w;
    if (t >= NN) return;
    const int lane = threadIdx.x & 31;
    const int beg = g_off[t], end = g_off[t + 1];
    const int deg = end - beg;
    const int h = lane >> 3;

    float4 acc = {0.f, 0.f, 0.f, 0.f};

    if (deg > 0) {
        float4 er4 = *(const float4*)(g_er + t * NH);  // broadcast
        const bool small = (deg <= 32);

        // ---- phase 1: ex = exp(lrelu(el+er)); sum denominators ----
        float4 d4 = {0.f, 0.f, 0.f, 0.f};
        int s_my = 0;
        float4 ex_my = {0.f, 0.f, 0.f, 0.f};

        int i0 = beg + lane;
        if (i0 < end) {
            s_my = __ldg(&g_csr_src[i0]);
            float4 l4 = *(const float4*)(g_el + s_my * NH);
            ex_my.x = __expf(lrelu(l4.x + er4.x));
            ex_my.y = __expf(lrelu(l4.y + er4.y));
            ex_my.z = __expf(lrelu(l4.z + er4.z));
            ex_my.w = __expf(lrelu(l4.w + er4.w));
            d4 = ex_my;
            if (!small) *(float4*)(g_e + (size_t)i0 * NH) = ex_my;
        }
        if (!small) {
            for (int i = i0 + 32; i < end; i += 32) {
                int s = __ldg(&g_csr_src[i]);
                float4 l4 = *(const float4*)(g_el + s * NH);
                float4 ex;
                ex.x = __expf(lrelu(l4.x + er4.x));
                ex.y = __expf(lrelu(l4.y + er4.y));
                ex.z = __expf(lrelu(l4.z + er4.z));
                ex.w = __expf(lrelu(l4.w + er4.w));
                d4.x += ex.x; d4.y += ex.y; d4.z += ex.z; d4.w += ex.w;
                *(float4*)(g_e + (size_t)i * NH) = ex;
            }
        }
#pragma unroll
        for (int off = 16; off; off >>= 1) {
            d4.x += __shfl_xor_sync(0xffffffffu, d4.x, off);
            d4.y += __shfl_xor_sync(0xffffffffu, d4.y, off);
            d4.z += __shfl_xor_sync(0xffffffffu, d4.z, off);
            d4.w += __shfl_xor_sync(0xffffffffu, d4.w, off);
        }
        float4 rd4;
        rd4.x = __frcp_rn(d4.x); rd4.y = __frcp_rn(d4.y);
        rd4.z = __frcp_rn(d4.z); rd4.w = __frcp_rn(d4.w);

        // ---- phase 2: aggregation via smem-staged (src, alpha) ----
        if (small) {
            if (lane < deg) {
                ssrc[w][lane] = s_my;
                salpha[w][lane][0] = ex_my.x * rd4.x;
                salpha[w][lane][1] = ex_my.y * rd4.y;
                salpha[w][lane][2] = ex_my.z * rd4.z;
                salpha[w][lane][3] = ex_my.w * rd4.w;
            }
            __syncwarp();
            for (int i = 0; i < deg; i++) {
                int si = ssrc[w][i];
                float alpha = salpha[w][i][h];
                float4 f = *(const float4*)(g_feat + (size_t)si * HD + lane * 4);
                acc.x = fmaf(f.x, alpha, acc.x);
                acc.y = fmaf(f.y, alpha, acc.y);
                acc.z = fmaf(f.z, alpha, acc.z);
                acc.w = fmaf(f.w, alpha, acc.w);
            }
        } else {
            for (int base = beg; base < end; base += 32) {
                int n = min(32, end - base);
                if (lane < n) {
                    int i = base + lane;
                    int s = __ldg(&g_csr_src[i]);
                    float4 ex = *(const float4*)(g_e + (size_t)i * NH);
                    ssrc[w][lane] = s;
                    salpha[w][lane][0] = ex.x * rd4.x;
                    salpha[w][lane][1] = ex.y * rd4.y;
                    salpha[w][lane][2] = ex.z * rd4.z;
                    salpha[w][lane][3] = ex.w * rd4.w;
                }
                __syncwarp();
                for (int i = 0; i < n; i++) {
                    int si = ssrc[w][i];
                    float alpha = salpha[w][i][h];
                    float4 f = *(const float4*)(g_feat + (size_t)si * HD + lane * 4);
                    acc.x = fmaf(f.x, alpha, acc.x);
                    acc.y = fmaf(f.y, alpha, acc.y);
                    acc.z = fmaf(f.z, alpha, acc.z);
                    acc.w = fmaf(f.w, alpha, acc.w);
                }
                __syncwarp();
            }
        }
    }

    // ---- epilogue: ELU (+ head-mean for layer 2) ----
    acc.x = (acc.x > 0.f) ? acc.x : expm1f(acc.x);
    acc.y = (acc.y > 0.f) ? acc.y : expm1f(acc.y);
    acc.z = (acc.z > 0.f) ? acc.z : expm1f(acc.z);
    acc.w = (acc.w > 0.f) ? acc.w : expm1f(acc.w);

    if (out == nullptr) {
        *(float4*)(g_h1 + (size_t)t * HD + lane * 4) = acc;
    } else {
#pragma unroll
        for (int off = 8; off <= 16; off <<= 1) {
            acc.x += __shfl_xor_sync(0xffffffffu, acc.x, off);
            acc.y += __shfl_xor_sync(0xffffffffu, acc.y, off);
            acc.z += __shfl_xor_sync(0xffffffffu, acc.z, off);
            acc.w += __shfl_xor_sync(0xffffffffu, acc.w, off);
        }
        if (lane < 8) {
            float4 o;
            o.x = 0.25f * acc.x; o.y = 0.25f * acc.y;
            o.z = 0.25f * acc.z; o.w = 0.25f * acc.w;
            *(float4*)(out + t * ND + lane * 4) = o;
        }
    }
}

// ---------------- launch ----------------------------------------------------
extern "C" void kernel_launch(void* const* d_in, const int* in_sizes, int n_in,
                              void* d_out, int out_size)
{
    const float* x   = (const float*)d_in[0];
    const void*  src = d_in[1];
    const void*  dst = d_in[2];
    const float* W1  = (const float*)d_in[3];
    const float* al1 = (const float*)d_in[4];
    const float* ar1 = (const float*)d_in[5];
    const float* W2  = (const float*)d_in[6];
    const float* al2 = (const float*)d_in[7];
    const float* ar2 = (const float*)d_in[8];
    float* out = (float*)d_out;

    const int edge_blocks = (EE + 255) / 256;
    const int node_blocks = (NN + 255) / 256;
    const int gemm_blocks = (NN + GN - 1) / GN;      // 782
    const int gat_blocks  = (NN + 7) / 8;

    // CSR build interleaved with layer-1 GEMM (gemm is independent of CSR;
    // placing it 4th also puts it under the ncu sampler).
    zero_cnt_kernel<<<node_blocks, 256>>>((const long long*)src);
    convert_kernel<<<edge_blocks, 256>>>(dst);
    scan_fused_kernel<<<1, STB>>>();
    gemm_kernel<<<gemm_blocks, 256>>>(x, W1, al1, ar1);
    scatter_kernel<<<edge_blocks, 256>>>(src);

    gat_edge_kernel<<<gat_blocks, 256>>>(nullptr);

    gemm_kernel<<<gemm_blocks, 256>>>(nullptr, W2, al2, ar2);
    gat_edge_kernel<<<gat_blocks, 256>>>(out);

    (void)in_sizes; (void)n_in; (void)out_size;
}